// round 17
// baseline (speedup 1.0000x reference)
#include <cuda_runtime.h>

#define HH 4096
#define WW 4096
#define NPIX (HH * WW)

// R9 structure, re-tiled: 32 quads x 8 rows per 256-thread block (warp = one
// contiguous 32-quad row segment). Boundary fraction of vertical re-reads
// drops 1/4 -> 1/8. Streaming hints for theta/out, branchless FSEL body,
// MLP=10 front-batched loads.

__global__ void __launch_bounds__(256, 7) nms_kernel(
    const float* __restrict__ img,
    const float* __restrict__ theta,
    float* __restrict__ out)
{
    unsigned tid = threadIdx.x;
    unsigned bx  = blockIdx.x & 31u;    // 32 tiles across (32 quads each)
    unsigned by  = blockIdx.x >> 5;     // 512 tiles down (8 rows each)
    unsigned tx  = tid & 31u;           // quad within row segment (warp-aligned)
    unsigned ty  = tid >> 5;            // row within tile (0..7)

    unsigned h    = (by << 3) + ty;
    unsigned w0   = ((bx << 5) + tx) << 2;
    unsigned base = (h << 12) + w0;

    if (h == 0 || h == HH - 1) {
        __stcs(reinterpret_cast<float4*>(out + base), make_float4(0.f, 0.f, 0.f, 0.f));
        return;
    }

    const float* pc = img + base;

    // ---- 10 independent loads, front-batched (MLP=10) ----
    const float4 t4 = __ldcs(reinterpret_cast<const float4*>(theta + base)); // read-once, evict-first
    const float4 c4 = __ldg(reinterpret_cast<const float4*>(pc));
    const float4 u4 = __ldg(reinterpret_cast<const float4*>(pc - WW));
    const float4 d4 = __ldg(reinterpret_cast<const float4*>(pc + WW));

    // corner clamps only bind for border-zeroed outputs; values never used.
    int uli = (int)base - WW - 1; if (uli < 0) uli = 0;
    int dri = (int)base + WW + 4; if (dri >= NPIX) dri = NPIX - 1;

    const float lft = __ldg(pc - 1);
    const float rgt = __ldg(pc + 4);
    const float ul  = __ldg(img + uli);
    const float ur  = __ldg(pc - WW + 4);
    const float dl  = __ldg(pc + WW - 1);
    const float dr  = __ldg(img + dri);

    const float RCP45 = 1.0f / 45.0f;   // RN(1/45)
    float o[4];

    // column layout (j = image column w0-1+j):
    // up:  ul  u4.x u4.y u4.z u4.w ur
    // ct:  lft c4.x c4.y c4.z c4.w rgt
    // dn:  dl  d4.x d4.y d4.z d4.w dr
    #define NMS_PX(i, UPL, UPC, UPR, CTL, CTC, CTR, DNL, DNC, DNR, TH)          \
    {                                                                            \
        float deg  = __fmul_rn((TH), 57.29577951308232f);                        \
        float degp = __fadd_rn(deg, 180.f);                                      \
        deg = (deg < 0.f) ? degp : deg;     /* FSEL, 4-cyc, not pred-guard */    \
        float q0 = __fmul_rn(deg, RCP45);                                        \
        float rr = __fmaf_rn(-45.f, q0, deg);                                    \
        float qf = __fmaf_rn(rr, RCP45, q0);                                     \
        int   k  = __float2int_rn(qf);      /* F2I.RNI = half-even = jnp.round */\
        bool p0 = (k == 0) | (k == 4);      /* 0 / 180 deg  */                   \
        bool p1 = (k == 1);                 /* 45           */                   \
        bool p2 = (k == 2);                 /* 90           */                   \
        float a_dn = p1 ? (DNR) : (p2 ? (DNC) : (DNL));                          \
        float a    = p0 ? (CTR) : a_dn;                                          \
        float b_up = p1 ? (UPL) : (p2 ? (UPC) : (UPR));                          \
        float b    = p0 ? (CTL) : b_up;                                          \
        o[i] = ((CTC) >= fmaxf(a, b)) ? (CTC) : 0.f;                             \
    }

    NMS_PX(0, ul,   u4.x, u4.y,  lft,  c4.x, c4.y,  dl,   d4.x, d4.y, t4.x)
    NMS_PX(1, u4.x, u4.y, u4.z,  c4.x, c4.y, c4.z,  d4.x, d4.y, d4.z, t4.y)
    NMS_PX(2, u4.y, u4.z, u4.w,  c4.y, c4.z, c4.w,  d4.y, d4.z, d4.w, t4.z)
    NMS_PX(3, u4.z, u4.w, ur,    c4.z, c4.w, rgt,   d4.z, d4.w, dr,   t4.w)

    #undef NMS_PX

    // left / right image borders
    if (w0 == 0)       o[0] = 0.f;
    if (w0 == WW - 4)  o[3] = 0.f;

    __stcs(reinterpret_cast<float4*>(out + base),
           make_float4(o[0], o[1], o[2], o[3]));     // never re-read: stream it
}

extern "C" void kernel_launch(void* const* d_in, const int* in_sizes, int n_in,
                              void* d_out, int out_size)
{
    const float* img   = (const float*)d_in[0];
    const float* theta = (const float*)d_in[1];
    float*       out   = (float*)d_out;

    const int grid = 32 * 512;   // 32 tiles-x * 512 tiles-y = 16384
    nms_kernel<<<grid, 256>>>(img, theta, out);
}